// round 9
// baseline (speedup 1.0000x reference)
#include <cuda_runtime.h>
#include <math.h>
#include <stdint.h>

// Problem constants
#define BATCH 2
#define SEQ   2048
#define DIM   2048
#define HEADS 32
#define DHEAD 64
#define ROWS  (BATCH * SEQ)          // 4096
#define DIM_INNER (HEADS * DHEAD)    // 2048

// ---------------- Scratch (static device globals — allocation-free) ----------
__device__ float g_xn[ROWS * DIM];
__device__ float g_q [ROWS * DIM_INNER];
__device__ float g_kv[ROWS * 2 * DIM_INNER];
__device__ float g_ao[ROWS * DIM_INNER];
__device__ float g_wq  [DIM * DIM_INNER];       // tf32-rounded weight copies
__device__ float g_wkv [DIM * 2 * DIM_INNER];
__device__ float g_wout[DIM_INNER * DIM];

// ============================ helpers ========================================
__device__ __forceinline__ float f2tf32(float x) {
    uint32_t u;
    asm("cvt.rna.tf32.f32 %0, %1;" : "=r"(u) : "f"(x));
    return __uint_as_float(u);
}
__device__ __forceinline__ void mma_tf32(float d[4],
                                         uint32_t a0, uint32_t a1, uint32_t a2, uint32_t a3,
                                         uint32_t b0, uint32_t b1) {
    asm volatile(
        "mma.sync.aligned.m16n8k8.row.col.f32.tf32.tf32.f32 "
        "{%0,%1,%2,%3}, {%4,%5,%6,%7}, {%8,%9}, {%0,%1,%2,%3};"
        : "+f"(d[0]), "+f"(d[1]), "+f"(d[2]), "+f"(d[3])
        : "r"(a0), "r"(a1), "r"(a2), "r"(a3), "r"(b0), "r"(b1));
}
__device__ __forceinline__ void cp16(uint32_t dst, const void* src) {
    asm volatile("cp.async.cg.shared.global [%0], [%1], 16;"
                 :: "r"(dst), "l"(__cvta_generic_to_global(src)));
}
__device__ __forceinline__ void cp_commit() {
    asm volatile("cp.async.commit_group;");
}
template<int N> __device__ __forceinline__ void cp_wait() {
    asm volatile("cp.async.wait_group %0;" :: "n"(N));
}

// ============================ RMSNorm (rounded output) =======================
__global__ void rmsnorm_kernel(const float* __restrict__ x,
                               const float* __restrict__ gamma,
                               float* __restrict__ xn) {
    int row = blockIdx.x;
    const float* xr = x + (size_t)row * DIM;
    float ss = 0.f;
    for (int i = threadIdx.x; i < DIM; i += blockDim.x) {
        float v = xr[i];
        ss += v * v;
    }
    __shared__ float red[32];
    int lane = threadIdx.x & 31, wid = threadIdx.x >> 5;
    #pragma unroll
    for (int off = 16; off > 0; off >>= 1) ss += __shfl_xor_sync(0xffffffffu, ss, off);
    if (lane == 0) red[wid] = ss;
    __syncthreads();
    if (wid == 0) {
        float v = (lane < (blockDim.x >> 5)) ? red[lane] : 0.f;
        #pragma unroll
        for (int off = 16; off > 0; off >>= 1) v += __shfl_xor_sync(0xffffffffu, v, off);
        if (lane == 0) red[0] = v;
    }
    __syncthreads();
    float norm = sqrtf(red[0]);
    float s = sqrtf((float)DIM) / fmaxf(norm, 1e-12f);
    float* xo = xn + (size_t)row * DIM;
    for (int i = threadIdx.x; i < DIM; i += blockDim.x)
        xo[i] = f2tf32(xr[i] * s * gamma[i]);
}

// =================== weight rounding copy (tf32 RNA) =========================
__global__ void round_copy(const float4* __restrict__ src,
                           float4* __restrict__ dst, int n4) {
    int i = blockIdx.x * blockDim.x + threadIdx.x;
    if (i >= n4) return;
    float4 v = src[i];
    v.x = f2tf32(v.x); v.y = f2tf32(v.y); v.z = f2tf32(v.z); v.w = f2tf32(v.w);
    dst[i] = v;
}

// ================ TF32 GEMM v2 (cp.async double-buffered) ====================
// C[M,N] = A[M,K] @ B[K,N]; inputs already tf32-rounded.
// round_out != 0 -> epilogue rounds C to tf32 (RNA).
#define TBM 128
#define TBN 128
#define TBK 32
#define ASTRIDE 36
#define BSTRIDE 132
#define GSST (TBM * ASTRIDE + TBK * BSTRIDE)          // floats per stage = 8832
#define GEMM_SMEM (2 * GSST * (int)sizeof(float))     // 70656 bytes

__global__ void __launch_bounds__(256, 2)
tf32_gemm2(const float* __restrict__ A, const float* __restrict__ B,
           float* __restrict__ C, int M, int N, int K, int round_out) {
    extern __shared__ float smp[];
    const int tid  = threadIdx.x;
    const int wid  = tid >> 5;
    const int lane = tid & 31;
    const int wm = (wid >> 2) * 64;
    const int wn = (wid & 3) * 32;
    const int brow = blockIdx.y * TBM;
    const int bcol = blockIdx.x * TBN;

    const int ar = tid >> 3;          // 0..31
    const int ac = (tid & 7) * 4;     // 0..28
    const float* Ap = A + (size_t)(brow + ar) * K + ac;
    const float* Bp = B + (size_t)ar * N + bcol + ac;

    const uint32_t smb = (uint32_t)__cvta_generic_to_shared(smp);

    float acc[16][4];
    #pragma unroll
    for (int i = 0; i < 16; i++)
        #pragma unroll
        for (int j = 0; j < 4; j++) acc[i][j] = 0.f;

    const int KT = K / TBK;

    #define GSTAGE(kt, p) do {                                                  \
        uint32_t as_ = smb + (uint32_t)((p) * GSST) * 4u;                       \
        uint32_t bs_ = as_ + TBM * ASTRIDE * 4u;                                \
        _Pragma("unroll")                                                       \
        for (int i_ = 0; i_ < 4; i_++)                                          \
            cp16(as_ + ((ar + 32 * i_) * ASTRIDE + ac) * 4u,                    \
                 Ap + (size_t)(kt) * TBK + (size_t)(32 * i_) * K);              \
        _Pragma("unroll")                                                       \
        for (int i_ = 0; i_ < 4; i_++)                                          \
            cp16(bs_ + (ar * BSTRIDE + ac + 32 * i_) * 4u,                      \
                 Bp + (size_t)(kt) * TBK * N + 32 * i_);                        \
    } while (0)

    GSTAGE(0, 0);
    cp_commit();

    for (int kt = 0; kt < KT; kt++) {
        if (kt + 1 < KT) {
            GSTAGE(kt + 1, (kt + 1) & 1);
            cp_commit();
            cp_wait<1>();
        } else {
            cp_wait<0>();
        }
        __syncthreads();

        const float* As_ = smp + (kt & 1) * GSST;
        const float* Bs_ = As_ + TBM * ASTRIDE;

        #pragma unroll
        for (int kk = 0; kk < TBK; kk += 8) {
            uint32_t afrag[4][4];
            #pragma unroll
            for (int mf = 0; mf < 4; mf++) {
                int r = wm + mf * 16 + (lane >> 2);
                int c = kk + (lane & 3);
                afrag[mf][0] = __float_as_uint(As_[r * ASTRIDE + c]);
                afrag[mf][1] = __float_as_uint(As_[(r + 8) * ASTRIDE + c]);
                afrag[mf][2] = __float_as_uint(As_[r * ASTRIDE + c + 4]);
                afrag[mf][3] = __float_as_uint(As_[(r + 8) * ASTRIDE + c + 4]);
            }
            #pragma unroll
            for (int nf = 0; nf < 4; nf++) {
                int col = wn + nf * 8 + (lane >> 2);
                int kr  = kk + (lane & 3);
                uint32_t b0 = __float_as_uint(Bs_[kr * BSTRIDE + col]);
                uint32_t b1 = __float_as_uint(Bs_[(kr + 4) * BSTRIDE + col]);
                #pragma unroll
                for (int mf = 0; mf < 4; mf++)
                    mma_tf32(acc[mf * 4 + nf], afrag[mf][0], afrag[mf][1],
                             afrag[mf][2], afrag[mf][3], b0, b1);
            }
        }
        __syncthreads();
    }

    #pragma unroll
    for (int mf = 0; mf < 4; mf++) {
        int row = brow + wm + mf * 16 + (lane >> 2);
        #pragma unroll
        for (int nf = 0; nf < 4; nf++) {
            int col = bcol + wn + nf * 8 + (lane & 3) * 2;
            float* c0 = C + (size_t)row * N + col;
            float* c1 = C + (size_t)(row + 8) * N + col;
            float v0 = acc[mf * 4 + nf][0], v1 = acc[mf * 4 + nf][1];
            float v2 = acc[mf * 4 + nf][2], v3 = acc[mf * 4 + nf][3];
            if (round_out) {
                v0 = f2tf32(v0); v1 = f2tf32(v1); v2 = f2tf32(v2); v3 = f2tf32(v3);
            }
            *(float2*)c0 = make_float2(v0, v1);
            *(float2*)c1 = make_float2(v2, v3);
        }
    }
}

// ===================== RoPE (rounds q, k; v already rounded) =================
__global__ void rope_kernel2(const float* __restrict__ rot,
                             float* __restrict__ q, float* __restrict__ kv) {
    int idx = blockIdx.x * blockDim.x + threadIdx.x;
    const int TOT = ROWS * HEADS * 32;
    if (idx >= TOT) return;
    int d = idx & 31;
    int h = (idx >> 5) & 31;
    int m = idx >> 10;
    int n = m & (SEQ - 1);

    float r0 = rot[n * DHEAD + d];
    float r1 = rot[n * DHEAD + d + 32];
    float c0 = cosf(r0), s0 = sinf(r0);
    float c1 = cosf(r1), s1 = sinf(r1);

    float* qp = q + (size_t)m * DIM_INNER + h * DHEAD;
    float q0 = qp[d], q1 = qp[d + 32];
    qp[d]      = f2tf32(q0 * c0 - q1 * s0);
    qp[d + 32] = f2tf32(q1 * c1 + q0 * s1);

    float* kp = kv + (size_t)m * (2 * DIM_INNER) + h * DHEAD;
    float k0 = kp[d], k1 = kp[d + 32];
    kp[d]      = f2tf32(k0 * c0 - k1 * s0);
    kp[d + 32] = f2tf32(k1 * c1 + k0 * s1);
}

// ====== Flash attention v4 (BM=64, P relayout via shuffles, 4 CTAs/SM) =======
// BM=BN=64, 4 warps; warp w owns rows [w*16, w*16+16).
// K double-buffered via cp.async; V prefetched one block ahead.
// P never touches smem: C-fragment -> A-fragment via register shuffles.
#define FKS 68
#define FVS 72
#define FKTILE (64 * FKS)  // floats per K buffer
#define FL_SMEM ((2 * FKTILE + 64 * FVS) * (int)sizeof(float))  // 53248

__global__ void __launch_bounds__(128, 4)
flash4(const float* __restrict__ q, const float* __restrict__ kv,
       float* __restrict__ ao) {
    extern __shared__ float sm[];
    float* Vs = sm + 2 * FKTILE;
    const uint32_t smb = (uint32_t)__cvta_generic_to_shared(sm);
    const uint32_t vsb = smb + 2u * FKTILE * 4u;

    const int bh = blockIdx.y;
    const int b  = bh >> 5;
    const int h  = bh & 31;
    const int i0 = (gridDim.x - 1 - blockIdx.x) * 64;  // heavy tiles first
    const int nj = i0 >> 6;

    const int tid  = threadIdx.x;
    const int wid  = tid >> 5;
    const int lane = tid & 31;
    const int qr   = lane >> 2;   // 0..7
    const int qc   = lane & 3;    // 0..3

    const int srow = tid >> 4;         // 0..7
    const int scol = (tid & 15) * 4;   // 0..60
    const float* kvbase = kv + (size_t)(b * SEQ) * (2 * DIM_INNER) + h * DHEAD;

    #define STAGE_K(jb, p) do {                                                  \
        const float* kb_ = kvbase + (size_t)((jb) * 64) * (2 * DIM_INNER);       \
        uint32_t kd_ = smb + (uint32_t)((p) * FKTILE) * 4u;                      \
        _Pragma("unroll")                                                        \
        for (int it_ = 0; it_ < 8; it_++) {                                      \
            int r_ = srow + 8 * it_;                                             \
            cp16(kd_ + (r_ * FKS + scol) * 4u,                                   \
                 kb_ + (size_t)r_ * (2 * DIM_INNER) + scol);                     \
        }                                                                        \
    } while (0)

    #define STAGE_V(jb) do {                                                     \
        const float* vb_ = kvbase + (size_t)((jb) * 64) * (2 * DIM_INNER) + DIM_INNER; \
        _Pragma("unroll")                                                        \
        for (int it_ = 0; it_ < 8; it_++) {                                      \
            int r_ = srow + 8 * it_;                                             \
            cp16(vsb + (r_ * FVS + scol) * 4u,                                   \
                 vb_ + (size_t)r_ * (2 * DIM_INNER) + scol);                     \
        }                                                                        \
    } while (0)

    // ---- Q A-fragments (pre-rounded; *0.125 exact) ----
    uint32_t qf[8][4];
    {
        const float* qb = q + (size_t)(b * SEQ + i0 + wid * 16) * DIM_INNER + h * DHEAD;
        #pragma unroll
        for (int kk = 0; kk < 8; kk++) {
            qf[kk][0] = __float_as_uint(qb[(size_t)qr * DIM_INNER + kk * 8 + qc] * 0.125f);
            qf[kk][1] = __float_as_uint(qb[(size_t)(qr + 8) * DIM_INNER + kk * 8 + qc] * 0.125f);
            qf[kk][2] = __float_as_uint(qb[(size_t)qr * DIM_INNER + kk * 8 + 4 + qc] * 0.125f);
            qf[kk][3] = __float_as_uint(qb[(size_t)(qr + 8) * DIM_INNER + kk * 8 + 4 + qc] * 0.125f);
        }
    }

    float oacc[8][4];
    #pragma unroll
    for (int i = 0; i < 8; i++)
        #pragma unroll
        for (int j = 0; j < 4; j++) oacc[i][j] = 0.f;
    float m_lo = -1e30f, m_hi = -1e30f, l_lo = 0.f, l_hi = 0.f;

    // prologue: preload K0, V0
    STAGE_K(0, 0); cp_commit();
    STAGE_V(0);    cp_commit();

    for (int jb = 0; jb <= nj; jb++) {
        const int p = jb & 1;
        const bool hn = (jb < nj);

        if (hn) { STAGE_K(jb + 1, p ^ 1); cp_commit(); }
        if (hn) cp_wait<2>(); else cp_wait<1>();
        __syncthreads();                         // K(jb) visible everywhere

        const float* Ks = sm + p * FKTILE;

        // ---- S = Q @ K^T ----
        float sacc[8][4];
        #pragma unroll
        for (int i = 0; i < 8; i++)
            #pragma unroll
            for (int j = 0; j < 4; j++) sacc[i][j] = 0.f;

        #pragma unroll
        for (int kk = 0; kk < 8; kk++) {
            #pragma unroll
            for (int nf = 0; nf < 8; nf++) {
                int col = nf * 8 + qr;
                uint32_t b0 = __float_as_uint(Ks[col * FKS + kk * 8 + qc]);
                uint32_t b1 = __float_as_uint(Ks[col * FKS + kk * 8 + 4 + qc]);
                mma_tf32(sacc[nf], qf[kk][0], qf[kk][1], qf[kk][2], qf[kk][3], b0, b1);
            }
        }

        // ---- causal mask (diagonal block only) ----
        if (jb == nj) {
            int gi_lo = wid * 16 + qr;
            int gi_hi = gi_lo + 8;
            #pragma unroll
            for (int nf = 0; nf < 8; nf++) {
                int gj = nf * 8 + qc * 2;
                if (gj     > gi_lo) sacc[nf][0] = -1e30f;
                if (gj + 1 > gi_lo) sacc[nf][1] = -1e30f;
                if (gj     > gi_hi) sacc[nf][2] = -1e30f;
                if (gj + 1 > gi_hi) sacc[nf][3] = -1e30f;
            }
        }

        // ---- online softmax ----
        float mx_lo = -1e30f, mx_hi = -1e30f;
        #pragma unroll
        for (int nf = 0; nf < 8; nf++) {
            mx_lo = fmaxf(mx_lo, fmaxf(sacc[nf][0], sacc[nf][1]));
            mx_hi = fmaxf(mx_hi, fmaxf(sacc[nf][2], sacc[nf][3]));
        }
        mx_lo = fmaxf(mx_lo, __shfl_xor_sync(0xffffffffu, mx_lo, 1));
        mx_lo = fmaxf(mx_lo, __shfl_xor_sync(0xffffffffu, mx_lo, 2));
        mx_hi = fmaxf(mx_hi, __shfl_xor_sync(0xffffffffu, mx_hi, 1));
        mx_hi = fmaxf(mx_hi, __shfl_xor_sync(0xffffffffu, mx_hi, 2));

        float mn_lo = fmaxf(m_lo, mx_lo);
        float mn_hi = fmaxf(m_hi, mx_hi);
        float so_lo = __expf(m_lo - mn_lo);
        float so_hi = __expf(m_hi - mn_hi);

        float sum_lo = 0.f, sum_hi = 0.f;
        #pragma unroll
        for (int nf = 0; nf < 8; nf++) {
            sacc[nf][0] = __expf(sacc[nf][0] - mn_lo); sum_lo += sacc[nf][0];
            sacc[nf][1] = __expf(sacc[nf][1] - mn_lo); sum_lo += sacc[nf][1];
            sacc[nf][2] = __expf(sacc[nf][2] - mn_hi); sum_hi += sacc[nf][2];
            sacc[nf][3] = __expf(sacc[nf][3] - mn_hi); sum_hi += sacc[nf][3];
        }
        sum_lo += __shfl_xor_sync(0xffffffffu, sum_lo, 1);
        sum_lo += __shfl_xor_sync(0xffffffffu, sum_lo, 2);
        sum_hi += __shfl_xor_sync(0xffffffffu, sum_hi, 1);
        sum_hi += __shfl_xor_sync(0xffffffffu, sum_hi, 2);

        l_lo = l_lo * so_lo + sum_lo;  m_lo = mn_lo;
        l_hi = l_hi * so_hi + sum_hi;  m_hi = mn_hi;

        #pragma unroll
        for (int nf = 0; nf < 8; nf++) {
            oacc[nf][0] *= so_lo; oacc[nf][1] *= so_lo;
            oacc[nf][2] *= so_hi; oacc[nf][3] *= so_hi;
        }

        if (hn) cp_wait<1>(); else cp_wait<0>();
        __syncthreads();                         // V(jb) visible everywhere

        // ---- O += P @ V  (P relayout: C-frag -> A-frag via shuffles) ----
        const int s0 = (qr << 2) | (qc >> 1);    // source lane for cols 0..3
        const int s2 = s0 + 2;                   // source lane for cols 4..7
        const bool odd = (qc & 1);
        #pragma unroll
        for (int kk = 0; kk < 8; kk++) {
            // round P to tf32 in registers (bit-identical to old smem path)
            float p0 = f2tf32(sacc[kk][0]);
            float p1 = f2tf32(sacc[kk][1]);
            float p2 = f2tf32(sacc[kk][2]);
            float p3 = f2tf32(sacc[kk][3]);

            float v00 = __shfl_sync(0xffffffffu, p0, s0);
            float v01 = __shfl_sync(0xffffffffu, p1, s0);
            uint32_t a0 = __float_as_uint(odd ? v01 : v00);
            float v10 = __shfl_sync(0xffffffffu, p2, s0);
            float v11 = __shfl_sync(0xffffffffu, p3, s0);
            uint32_t a1 = __float_as_uint(odd ? v11 : v10);
            float v20 = __shfl_sync(0xffffffffu, p0, s2);
            float v21 = __shfl_sync(0xffffffffu, p1, s2);
            uint32_t a2 = __float_as_uint(odd ? v21 : v20);
            float v30 = __shfl_sync(0xffffffffu, p2, s2);
            float v31 = __shfl_sync(0xffffffffu, p3, s2);
            uint32_t a3 = __float_as_uint(odd ? v31 : v30);

            #pragma unroll
            for (int nf = 0; nf < 8; nf++) {
                int col = nf * 8 + qr;
                uint32_t b0 = __float_as_uint(Vs[(kk * 8 + qc) * FVS + col]);
                uint32_t b1 = __float_as_uint(Vs[(kk * 8 + 4 + qc) * FVS + col]);
                mma_tf32(oacc[nf], a0, a1, a2, a3, b0, b1);
            }
        }
        __syncthreads();                         // all warps done reading Vs

        if (hn) { STAGE_V(jb + 1); cp_commit(); }
    }

    // ---- epilogue: normalize, round (feeds out-proj), store ----
    float inv_lo = 1.f / l_lo;
    float inv_hi = 1.f / l_hi;
    {
        int r_lo = b * SEQ + i0 + wid * 16 + qr;
        float* o0 = ao + (size_t)r_lo * DIM_INNER + h * DHEAD + qc * 2;
        float* o1 = ao + (size_t)(r_lo + 8) * DIM_INNER + h * DHEAD + qc * 2;
        #pragma unroll
        for (int nf = 0; nf < 8; nf++) {
            *(float2*)(o0 + nf * 8) = make_float2(f2tf32(oacc[nf][0] * inv_lo),
                                                  f2tf32(oacc[nf][1] * inv_lo));
            *(float2*)(o1 + nf * 8) = make_float2(f2tf32(oacc[nf][2] * inv_hi),
                                                  f2tf32(oacc[nf][3] * inv_hi));
        }
    }
}

// ============================ Launch =========================================
extern "C" void kernel_launch(void* const* d_in, const int* in_sizes, int n_in,
                              void* d_out, int out_size) {
    const float* x     = (const float*)d_in[0];
    const float* rot   = (const float*)d_in[1];
    const float* gamma = (const float*)d_in[2];
    const float* Wq    = (const float*)d_in[3];
    const float* Wkv   = (const float*)d_in[4];
    const float* Wout  = (const float*)d_in[5];
    float* out = (float*)d_out;

    float *xn, *q, *kv, *ao, *wq, *wkv, *wout;
    cudaGetSymbolAddress((void**)&xn,   g_xn);
    cudaGetSymbolAddress((void**)&q,    g_q);
    cudaGetSymbolAddress((void**)&kv,   g_kv);
    cudaGetSymbolAddress((void**)&ao,   g_ao);
    cudaGetSymbolAddress((void**)&wq,   g_wq);
    cudaGetSymbolAddress((void**)&wkv,  g_wkv);
    cudaGetSymbolAddress((void**)&wout, g_wout);

    cudaFuncSetAttribute(tf32_gemm2,
                         cudaFuncAttributeMaxDynamicSharedMemorySize, GEMM_SMEM);
    cudaFuncSetAttribute(flash4,
                         cudaFuncAttributeMaxDynamicSharedMemorySize, FL_SMEM);

    // 0) tf32-rounded weight copies
    {
        int n4q = DIM * DIM_INNER / 4;
        round_copy<<<(n4q + 255) / 256, 256>>>((const float4*)Wq,  (float4*)wq,  n4q);
        int n4kv = DIM * 2 * DIM_INNER / 4;
        round_copy<<<(n4kv + 255) / 256, 256>>>((const float4*)Wkv, (float4*)wkv, n4kv);
        int n4o = DIM_INNER * DIM / 4;
        round_copy<<<(n4o + 255) / 256, 256>>>((const float4*)Wout, (float4*)wout, n4o);
    }

    // 1) RMSNorm (tf32-rounded output)
    rmsnorm_kernel<<<ROWS, 256>>>(x, gamma, xn);

    // 2) projections (cp.async tf32 GEMM; outputs rounded -> v pre-rounded)
    tf32_gemm2<<<dim3(DIM_INNER / TBN, ROWS / TBM), 256, GEMM_SMEM>>>(
        xn, wq, q, ROWS, DIM_INNER, DIM, 1);
    tf32_gemm2<<<dim3(2 * DIM_INNER / TBN, ROWS / TBM), 256, GEMM_SMEM>>>(
        xn, wkv, kv, ROWS, 2 * DIM_INNER, DIM, 1);

    // 3) RoPE (rounds q, k after rotation)
    {
        int tot = ROWS * HEADS * 32;
        rope_kernel2<<<(tot + 255) / 256, 256>>>(rot, q, kv);
    }

    // 4) causal flash attention (BM=64, P-in-registers, 4 CTAs/SM)
    flash4<<<dim3(SEQ / 64, BATCH * HEADS), 128, FL_SMEM>>>(q, kv, ao);

    // 5) out projection (raw fp32 output)
    tf32_gemm2<<<dim3(DIM / TBN, ROWS / TBM), 256, GEMM_SMEM>>>(
        ao, wout, out, ROWS, DIM, DIM, 0);
}

// round 10
// speedup vs baseline: 1.1504x; 1.1504x over previous
#include <cuda_runtime.h>
#include <cuda_fp16.h>
#include <math.h>
#include <stdint.h>

// Problem constants
#define BATCH 2
#define SEQ   2048
#define DIM   2048
#define HEADS 32
#define DHEAD 64
#define ROWS  (BATCH * SEQ)          // 4096
#define DIM_INNER (HEADS * DHEAD)    // 2048

// ---------------- Scratch (static device globals — allocation-free) ----------
__device__ float  g_xn[ROWS * DIM];
__device__ float  g_q [ROWS * DIM_INNER];
__device__ float  g_kv[ROWS * 2 * DIM_INNER];
__device__ float  g_ao[ROWS * DIM_INNER];
__device__ float  g_wq  [DIM * DIM_INNER];        // tf32-rounded weights
__device__ float  g_wkv [DIM * 2 * DIM_INNER];
__device__ float  g_wout[DIM_INNER * DIM];
__device__ __half g_qh[ROWS * DIM_INNER];         // fp16 q (pre-scaled, post-rope)
__device__ __half g_kh[ROWS * DIM_INNER];         // fp16 k (post-rope)
__device__ __half g_vt[BATCH * HEADS * DHEAD * SEQ]; // fp16 V transposed [b,h,d,n]

// ============================ helpers ========================================
__device__ __forceinline__ float f2tf32(float x) {
    uint32_t u;
    asm("cvt.rna.tf32.f32 %0, %1;" : "=r"(u) : "f"(x));
    return __uint_as_float(u);
}
__device__ __forceinline__ void mma_tf32(float d[4],
                                         uint32_t a0, uint32_t a1, uint32_t a2, uint32_t a3,
                                         uint32_t b0, uint32_t b1) {
    asm volatile(
        "mma.sync.aligned.m16n8k8.row.col.f32.tf32.tf32.f32 "
        "{%0,%1,%2,%3}, {%4,%5,%6,%7}, {%8,%9}, {%0,%1,%2,%3};"
        : "+f"(d[0]), "+f"(d[1]), "+f"(d[2]), "+f"(d[3])
        : "r"(a0), "r"(a1), "r"(a2), "r"(a3), "r"(b0), "r"(b1));
}
__device__ __forceinline__ void mma_f16(float d[4],
                                        uint32_t a0, uint32_t a1, uint32_t a2, uint32_t a3,
                                        uint32_t b0, uint32_t b1) {
    asm volatile(
        "mma.sync.aligned.m16n8k16.row.col.f32.f16.f16.f32 "
        "{%0,%1,%2,%3}, {%4,%5,%6,%7}, {%8,%9}, {%0,%1,%2,%3};"
        : "+f"(d[0]), "+f"(d[1]), "+f"(d[2]), "+f"(d[3])
        : "r"(a0), "r"(a1), "r"(a2), "r"(a3), "r"(b0), "r"(b1));
}
__device__ __forceinline__ uint32_t packh2(float a, float b) {
    __half2 h = __floats2half2_rn(a, b);
    return *(uint32_t*)&h;
}
__device__ __forceinline__ void cp16(uint32_t dst, const void* src) {
    asm volatile("cp.async.cg.shared.global [%0], [%1], 16;"
                 :: "r"(dst), "l"(__cvta_generic_to_global(src)));
}
__device__ __forceinline__ void cp_commit() {
    asm volatile("cp.async.commit_group;");
}
template<int N> __device__ __forceinline__ void cp_wait() {
    asm volatile("cp.async.wait_group %0;" :: "n"(N));
}

// ============================ RMSNorm (tf32-rounded out) =====================
__global__ void rmsnorm_kernel(const float* __restrict__ x,
                               const float* __restrict__ gamma,
                               float* __restrict__ xn) {
    int row = blockIdx.x;
    const float* xr = x + (size_t)row * DIM;
    float ss = 0.f;
    for (int i = threadIdx.x; i < DIM; i += blockDim.x) {
        float v = xr[i];
        ss += v * v;
    }
    __shared__ float red[32];
    int lane = threadIdx.x & 31, wid = threadIdx.x >> 5;
    #pragma unroll
    for (int off = 16; off > 0; off >>= 1) ss += __shfl_xor_sync(0xffffffffu, ss, off);
    if (lane == 0) red[wid] = ss;
    __syncthreads();
    if (wid == 0) {
        float v = (lane < (blockDim.x >> 5)) ? red[lane] : 0.f;
        #pragma unroll
        for (int off = 16; off > 0; off >>= 1) v += __shfl_xor_sync(0xffffffffu, v, off);
        if (lane == 0) red[0] = v;
    }
    __syncthreads();
    float norm = sqrtf(red[0]);
    float s = sqrtf((float)DIM) / fmaxf(norm, 1e-12f);
    float* xo = xn + (size_t)row * DIM;
    for (int i = threadIdx.x; i < DIM; i += blockDim.x)
        xo[i] = f2tf32(xr[i] * s * gamma[i]);
}

// =================== weight rounding copy (tf32 RNA) =========================
__global__ void round_copy(const float4* __restrict__ src,
                           float4* __restrict__ dst, int n4) {
    int i = blockIdx.x * blockDim.x + threadIdx.x;
    if (i >= n4) return;
    float4 v = src[i];
    v.x = f2tf32(v.x); v.y = f2tf32(v.y); v.z = f2tf32(v.z); v.w = f2tf32(v.w);
    dst[i] = v;
}

// ================ TF32 GEMM v2 (cp.async double-buffered) ====================
#define TBM 128
#define TBN 128
#define TBK 32
#define ASTRIDE 36
#define BSTRIDE 132
#define GSST (TBM * ASTRIDE + TBK * BSTRIDE)          // 8832 floats
#define GEMM_SMEM (2 * GSST * (int)sizeof(float))     // 70656 bytes

__global__ void __launch_bounds__(256, 2)
tf32_gemm2(const float* __restrict__ A, const float* __restrict__ B,
           float* __restrict__ C, int M, int N, int K, int round_out) {
    extern __shared__ float smp[];
    const int tid  = threadIdx.x;
    const int wid  = tid >> 5;
    const int lane = tid & 31;
    const int wm = (wid >> 2) * 64;
    const int wn = (wid & 3) * 32;
    const int brow = blockIdx.y * TBM;
    const int bcol = blockIdx.x * TBN;

    const int ar = tid >> 3;
    const int ac = (tid & 7) * 4;
    const float* Ap = A + (size_t)(brow + ar) * K + ac;
    const float* Bp = B + (size_t)ar * N + bcol + ac;

    const uint32_t smb = (uint32_t)__cvta_generic_to_shared(smp);

    float acc[16][4];
    #pragma unroll
    for (int i = 0; i < 16; i++)
        #pragma unroll
        for (int j = 0; j < 4; j++) acc[i][j] = 0.f;

    const int KT = K / TBK;

    #define GSTAGE(kt, p) do {                                                  \
        uint32_t as_ = smb + (uint32_t)((p) * GSST) * 4u;                       \
        uint32_t bs_ = as_ + TBM * ASTRIDE * 4u;                                \
        _Pragma("unroll")                                                       \
        for (int i_ = 0; i_ < 4; i_++)                                          \
            cp16(as_ + ((ar + 32 * i_) * ASTRIDE + ac) * 4u,                    \
                 Ap + (size_t)(kt) * TBK + (size_t)(32 * i_) * K);              \
        _Pragma("unroll")                                                       \
        for (int i_ = 0; i_ < 4; i_++)                                          \
            cp16(bs_ + (ar * BSTRIDE + ac + 32 * i_) * 4u,                      \
                 Bp + (size_t)(kt) * TBK * N + 32 * i_);                        \
    } while (0)

    GSTAGE(0, 0);
    cp_commit();

    for (int kt = 0; kt < KT; kt++) {
        if (kt + 1 < KT) {
            GSTAGE(kt + 1, (kt + 1) & 1);
            cp_commit();
            cp_wait<1>();
        } else {
            cp_wait<0>();
        }
        __syncthreads();

        const float* As_ = smp + (kt & 1) * GSST;
        const float* Bs_ = As_ + TBM * ASTRIDE;

        #pragma unroll
        for (int kk = 0; kk < TBK; kk += 8) {
            uint32_t afrag[4][4];
            #pragma unroll
            for (int mf = 0; mf < 4; mf++) {
                int r = wm + mf * 16 + (lane >> 2);
                int c = kk + (lane & 3);
                afrag[mf][0] = __float_as_uint(As_[r * ASTRIDE + c]);
                afrag[mf][1] = __float_as_uint(As_[(r + 8) * ASTRIDE + c]);
                afrag[mf][2] = __float_as_uint(As_[r * ASTRIDE + c + 4]);
                afrag[mf][3] = __float_as_uint(As_[(r + 8) * ASTRIDE + c + 4]);
            }
            #pragma unroll
            for (int nf = 0; nf < 4; nf++) {
                int col = wn + nf * 8 + (lane >> 2);
                int kr  = kk + (lane & 3);
                uint32_t b0 = __float_as_uint(Bs_[kr * BSTRIDE + col]);
                uint32_t b1 = __float_as_uint(Bs_[(kr + 4) * BSTRIDE + col]);
                #pragma unroll
                for (int mf = 0; mf < 4; mf++)
                    mma_tf32(acc[mf * 4 + nf], afrag[mf][0], afrag[mf][1],
                             afrag[mf][2], afrag[mf][3], b0, b1);
            }
        }
        __syncthreads();
    }

    #pragma unroll
    for (int mf = 0; mf < 4; mf++) {
        int row = brow + wm + mf * 16 + (lane >> 2);
        #pragma unroll
        for (int nf = 0; nf < 4; nf++) {
            int col = bcol + wn + nf * 8 + (lane & 3) * 2;
            float* c0 = C + (size_t)row * N + col;
            float* c1 = C + (size_t)(row + 8) * N + col;
            float v0 = acc[mf * 4 + nf][0], v1 = acc[mf * 4 + nf][1];
            float v2 = acc[mf * 4 + nf][2], v3 = acc[mf * 4 + nf][3];
            if (round_out) {
                v0 = f2tf32(v0); v1 = f2tf32(v1); v2 = f2tf32(v2); v3 = f2tf32(v3);
            }
            *(float2*)c0 = make_float2(v0, v1);
            *(float2*)c1 = make_float2(v2, v3);
        }
    }
}

// ======== RoPE -> fp16 (q pre-scaled by 1/8; k plain); kv untouched ==========
__global__ void rope_half(const float* __restrict__ rot,
                          const float* __restrict__ q, const float* __restrict__ kv,
                          __half* __restrict__ qh, __half* __restrict__ kh) {
    int idx = blockIdx.x * blockDim.x + threadIdx.x;
    const int TOT = ROWS * HEADS * 32;
    if (idx >= TOT) return;
    int d = idx & 31;
    int h = (idx >> 5) & 31;
    int m = idx >> 10;
    int n = m & (SEQ - 1);

    float r0 = rot[n * DHEAD + d];
    float r1 = rot[n * DHEAD + d + 32];
    float c0 = cosf(r0), s0 = sinf(r0);
    float c1 = cosf(r1), s1 = sinf(r1);

    const float* qp = q + (size_t)m * DIM_INNER + h * DHEAD;
    float q0 = qp[d], q1 = qp[d + 32];
    __half* qo = qh + (size_t)m * DIM_INNER + h * DHEAD;
    qo[d]      = __float2half((q0 * c0 - q1 * s0) * 0.125f);
    qo[d + 32] = __float2half((q1 * c1 + q0 * s1) * 0.125f);

    const float* kp = kv + (size_t)m * (2 * DIM_INNER) + h * DHEAD;
    float k0 = kp[d], k1 = kp[d + 32];
    __half* ko = kh + (size_t)m * DIM_INNER + h * DHEAD;
    ko[d]      = __float2half(k0 * c0 - k1 * s0);
    ko[d + 32] = __float2half(k1 * c1 + k0 * s1);
}

// ============ V transpose: kv fp32 [n][2048+h*64+d] -> vt fp16 [b,h,d,n] =====
__global__ void vtrans_kernel(const float* __restrict__ kv, __half* __restrict__ vt) {
    __shared__ float ts[64][65];
    const int bh = blockIdx.x >> 5;          // 0..63
    const int jt = blockIdx.x & 31;          // 64-wide n tile
    const int b  = bh >> 5;
    const int h  = bh & 31;
    const int tid = threadIdx.x;             // 256

    const float* src = kv + (size_t)(b * SEQ + jt * 64) * (2 * DIM_INNER)
                          + DIM_INNER + h * DHEAD;
    #pragma unroll
    for (int i = 0; i < 16; i++) {
        int idx = tid + i * 256;             // 0..4095
        int r = idx >> 6;                    // n within tile
        int c = idx & 63;                    // d
        ts[c][r] = src[(size_t)r * (2 * DIM_INNER) + c];
    }
    __syncthreads();
    __half* dst = vt + ((size_t)bh * DHEAD) * SEQ + jt * 64;
    #pragma unroll
    for (int i = 0; i < 16; i++) {
        int idx = tid + i * 256;
        int dr = idx >> 6;                   // d
        int jc = idx & 63;                   // n within tile
        dst[(size_t)dr * SEQ + jc] = __float2half(ts[dr][jc]);
    }
}

// ========== Flash attention v5 (fp16 m16n8k16, P in registers) ===============
// BM=BN=64, 4 warps; warp w owns rows [w*16, w*16+16).
// K fp16 double-buffered; V^T fp16 prefetched one block ahead.
#define HKS 72                     // K/Vt row stride (halves)
#define HKTILE (64 * HKS)          // halves per K buffer
#define FL5_SMEM ((3 * HKTILE) * (int)sizeof(__half))   // 27648 bytes

__global__ void __launch_bounds__(128, 4)
flash5(const __half* __restrict__ qh, const __half* __restrict__ kh,
       const __half* __restrict__ vt, float* __restrict__ ao) {
    extern __shared__ __half smh[];
    __half* Vt = smh + 2 * HKTILE;
    const uint32_t smb = (uint32_t)__cvta_generic_to_shared(smh);
    const uint32_t vtb = smb + 2u * HKTILE * 2u;

    const int bh = blockIdx.y;
    const int b  = bh >> 5;
    const int h  = bh & 31;
    const int i0 = (gridDim.x - 1 - blockIdx.x) * 64;  // heavy tiles first
    const int nj = i0 >> 6;

    const int tid  = threadIdx.x;
    const int wid  = tid >> 5;
    const int lane = tid & 31;
    const int qr   = lane >> 2;   // 0..7
    const int qc   = lane & 3;    // 0..3

    // staging: 64 rows x 8 chunks(16B) per tile; 128 threads x 4 iters
    const int srow = tid >> 3;          // 0..15
    const int schk = (tid & 7) * 8;     // halves offset 0..56
    const __half* kbase  = kh + (size_t)(b * SEQ) * DIM_INNER + h * DHEAD;
    const __half* vtbase = vt + ((size_t)bh * DHEAD) * SEQ;

    #define STAGE_KH(jb, p) do {                                                 \
        const __half* kb_ = kbase + (size_t)((jb) * 64) * DIM_INNER;             \
        uint32_t kd_ = smb + (uint32_t)((p) * HKTILE) * 2u;                      \
        _Pragma("unroll")                                                        \
        for (int it_ = 0; it_ < 4; it_++) {                                      \
            int r_ = srow + 16 * it_;                                            \
            cp16(kd_ + (r_ * HKS + schk) * 2u,                                   \
                 kb_ + (size_t)r_ * DIM_INNER + schk);                           \
        }                                                                        \
    } while (0)

    #define STAGE_VT(jb) do {                                                    \
        const __half* vb_ = vtbase + (jb) * 64;                                  \
        _Pragma("unroll")                                                        \
        for (int it_ = 0; it_ < 4; it_++) {                                      \
            int r_ = srow + 16 * it_;                                            \
            cp16(vtb + (r_ * HKS + schk) * 2u,                                   \
                 vb_ + (size_t)r_ * SEQ + schk);                                 \
        }                                                                        \
    } while (0)

    // ---- Q A-fragments (fp16, pre-scaled) ----
    uint32_t qf[4][4];
    {
        const __half* qb = qh + (size_t)(b * SEQ + i0 + wid * 16) * DIM_INNER + h * DHEAD;
        #pragma unroll
        for (int kk = 0; kk < 4; kk++) {
            int c = kk * 16 + 2 * qc;
            qf[kk][0] = *(const uint32_t*)(qb + (size_t)qr * DIM_INNER + c);
            qf[kk][1] = *(const uint32_t*)(qb + (size_t)(qr + 8) * DIM_INNER + c);
            qf[kk][2] = *(const uint32_t*)(qb + (size_t)qr * DIM_INNER + c + 8);
            qf[kk][3] = *(const uint32_t*)(qb + (size_t)(qr + 8) * DIM_INNER + c + 8);
        }
    }

    float oacc[8][4];
    #pragma unroll
    for (int i = 0; i < 8; i++)
        #pragma unroll
        for (int j = 0; j < 4; j++) oacc[i][j] = 0.f;
    float m_lo = -1e30f, m_hi = -1e30f, l_lo = 0.f, l_hi = 0.f;

    // prologue: preload K0, V0
    STAGE_KH(0, 0); cp_commit();
    STAGE_VT(0);    cp_commit();

    for (int jb = 0; jb <= nj; jb++) {
        const int p = jb & 1;
        const bool hn = (jb < nj);

        if (hn) { STAGE_KH(jb + 1, p ^ 1); cp_commit(); }
        if (hn) cp_wait<2>(); else cp_wait<1>();
        __syncthreads();                         // K(jb) visible

        const __half* Ks = smh + p * HKTILE;

        // ---- S = Q @ K^T ----
        float sacc[8][4];
        #pragma unroll
        for (int i = 0; i < 8; i++)
            #pragma unroll
            for (int j = 0; j < 4; j++) sacc[i][j] = 0.f;

        #pragma unroll
        for (int kk = 0; kk < 4; kk++) {
            #pragma unroll
            for (int nf = 0; nf < 8; nf++) {
                const __half* kr = Ks + (nf * 8 + qr) * HKS + kk * 16 + 2 * qc;
                uint32_t b0 = *(const uint32_t*)kr;
                uint32_t b1 = *(const uint32_t*)(kr + 8);
                mma_f16(sacc[nf], qf[kk][0], qf[kk][1], qf[kk][2], qf[kk][3], b0, b1);
            }
        }

        // ---- causal mask (diagonal block only) ----
        if (jb == nj) {
            int gi_lo = wid * 16 + qr;
            int gi_hi = gi_lo + 8;
            #pragma unroll
            for (int nf = 0; nf < 8; nf++) {
                int gj = nf * 8 + qc * 2;
                if (gj     > gi_lo) sacc[nf][0] = -1e30f;
                if (gj + 1 > gi_lo) sacc[nf][1] = -1e30f;
                if (gj     > gi_hi) sacc[nf][2] = -1e30f;
                if (gj + 1 > gi_hi) sacc[nf][3] = -1e30f;
            }
        }

        // ---- online softmax ----
        float mx_lo = -1e30f, mx_hi = -1e30f;
        #pragma unroll
        for (int nf = 0; nf < 8; nf++) {
            mx_lo = fmaxf(mx_lo, fmaxf(sacc[nf][0], sacc[nf][1]));
            mx_hi = fmaxf(mx_hi, fmaxf(sacc[nf][2], sacc[nf][3]));
        }
        mx_lo = fmaxf(mx_lo, __shfl_xor_sync(0xffffffffu, mx_lo, 1));
        mx_lo = fmaxf(mx_lo, __shfl_xor_sync(0xffffffffu, mx_lo, 2));
        mx_hi = fmaxf(mx_hi, __shfl_xor_sync(0xffffffffu, mx_hi, 1));
        mx_hi = fmaxf(mx_hi, __shfl_xor_sync(0xffffffffu, mx_hi, 2));

        float mn_lo = fmaxf(m_lo, mx_lo);
        float mn_hi = fmaxf(m_hi, mx_hi);
        float so_lo = __expf(m_lo - mn_lo);
        float so_hi = __expf(m_hi - mn_hi);

        float sum_lo = 0.f, sum_hi = 0.f;
        #pragma unroll
        for (int nf = 0; nf < 8; nf++) {
            sacc[nf][0] = __expf(sacc[nf][0] - mn_lo); sum_lo += sacc[nf][0];
            sacc[nf][1] = __expf(sacc[nf][1] - mn_lo); sum_lo += sacc[nf][1];
            sacc[nf][2] = __expf(sacc[nf][2] - mn_hi); sum_hi += sacc[nf][2];
            sacc[nf][3] = __expf(sacc[nf][3] - mn_hi); sum_hi += sacc[nf][3];
        }
        sum_lo += __shfl_xor_sync(0xffffffffu, sum_lo, 1);
        sum_lo += __shfl_xor_sync(0xffffffffu, sum_lo, 2);
        sum_hi += __shfl_xor_sync(0xffffffffu, sum_hi, 1);
        sum_hi += __shfl_xor_sync(0xffffffffu, sum_hi, 2);

        l_lo = l_lo * so_lo + sum_lo;  m_lo = mn_lo;
        l_hi = l_hi * so_hi + sum_hi;  m_hi = mn_hi;

        #pragma unroll
        for (int nf = 0; nf < 8; nf++) {
            oacc[nf][0] *= so_lo; oacc[nf][1] *= so_lo;
            oacc[nf][2] *= so_hi; oacc[nf][3] *= so_hi;
        }

        if (hn) cp_wait<1>(); else cp_wait<0>();
        __syncthreads();                         // V(jb) visible

        // ---- O += P @ V : A-frag = packed pairs of S C-frags ----
        #pragma unroll
        for (int kk = 0; kk < 4; kk++) {
            uint32_t a0 = packh2(sacc[2 * kk][0],     sacc[2 * kk][1]);
            uint32_t a1 = packh2(sacc[2 * kk][2],     sacc[2 * kk][3]);
            uint32_t a2 = packh2(sacc[2 * kk + 1][0], sacc[2 * kk + 1][1]);
            uint32_t a3 = packh2(sacc[2 * kk + 1][2], sacc[2 * kk + 1][3]);
            #pragma unroll
            for (int nf = 0; nf < 8; nf++) {
                const __half* vr = Vt + (nf * 8 + qr) * HKS + kk * 16 + 2 * qc;
                uint32_t b0 = *(const uint32_t*)vr;
                uint32_t b1 = *(const uint32_t*)(vr + 8);
                mma_f16(oacc[nf], a0, a1, a2, a3, b0, b1);
            }
        }
        __syncthreads();                         // Vt reusable

        if (hn) { STAGE_VT(jb + 1); cp_commit(); }
    }

    // ---- epilogue: normalize, round (feeds tf32 out-proj), store ----
    float inv_lo = 1.f / l_lo;
    float inv_hi = 1.f / l_hi;
    {
        int r_lo = b * SEQ + i0 + wid * 16 + qr;
        float* o0 = ao + (size_t)r_lo * DIM_INNER + h * DHEAD + qc * 2;
        float* o1 = ao + (size_t)(r_lo + 8) * DIM_INNER + h * DHEAD + qc * 2;
        #pragma unroll
        for (int nf = 0; nf < 8; nf++) {
            *(float2*)(o0 + nf * 8) = make_float2(f2tf32(oacc[nf][0] * inv_lo),
                                                  f2tf32(oacc[nf][1] * inv_lo));
            *(float2*)(o1 + nf * 8) = make_float2(f2tf32(oacc[nf][2] * inv_hi),
                                                  f2tf32(oacc[nf][3] * inv_hi));
        }
    }
}

// ============================ Launch =========================================
extern "C" void kernel_launch(void* const* d_in, const int* in_sizes, int n_in,
                              void* d_out, int out_size) {
    const float* x     = (const float*)d_in[0];
    const float* rot   = (const float*)d_in[1];
    const float* gamma = (const float*)d_in[2];
    const float* Wq    = (const float*)d_in[3];
    const float* Wkv   = (const float*)d_in[4];
    const float* Wout  = (const float*)d_in[5];
    float* out = (float*)d_out;

    float *xn, *q, *kv, *ao, *wq, *wkv, *wout;
    __half *qhp, *khp, *vtp;
    cudaGetSymbolAddress((void**)&xn,   g_xn);
    cudaGetSymbolAddress((void**)&q,    g_q);
    cudaGetSymbolAddress((void**)&kv,   g_kv);
    cudaGetSymbolAddress((void**)&ao,   g_ao);
    cudaGetSymbolAddress((void**)&wq,   g_wq);
    cudaGetSymbolAddress((void**)&wkv,  g_wkv);
    cudaGetSymbolAddress((void**)&wout, g_wout);
    cudaGetSymbolAddress((void**)&qhp,  g_qh);
    cudaGetSymbolAddress((void**)&khp,  g_kh);
    cudaGetSymbolAddress((void**)&vtp,  g_vt);

    cudaFuncSetAttribute(tf32_gemm2,
                         cudaFuncAttributeMaxDynamicSharedMemorySize, GEMM_SMEM);
    cudaFuncSetAttribute(flash5,
                         cudaFuncAttributeMaxDynamicSharedMemorySize, FL5_SMEM);

    // 0) tf32-rounded weight copies
    {
        int n4q = DIM * DIM_INNER / 4;
        round_copy<<<(n4q + 255) / 256, 256>>>((const float4*)Wq,  (float4*)wq,  n4q);
        int n4kv = DIM * 2 * DIM_INNER / 4;
        round_copy<<<(n4kv + 255) / 256, 256>>>((const float4*)Wkv, (float4*)wkv, n4kv);
        int n4o = DIM_INNER * DIM / 4;
        round_copy<<<(n4o + 255) / 256, 256>>>((const float4*)Wout, (float4*)wout, n4o);
    }

    // 1) RMSNorm (tf32-rounded output)
    rmsnorm_kernel<<<ROWS, 256>>>(x, gamma, xn);

    // 2) projections (tf32 tensor cores; raw fp32 out, fp16 conversion follows)
    tf32_gemm2<<<dim3(DIM_INNER / TBN, ROWS / TBM), 256, GEMM_SMEM>>>(
        xn, wq, q, ROWS, DIM_INNER, DIM, 0);
    tf32_gemm2<<<dim3(2 * DIM_INNER / TBN, ROWS / TBM), 256, GEMM_SMEM>>>(
        xn, wkv, kv, ROWS, 2 * DIM_INNER, DIM, 0);

    // 3) RoPE -> fp16 q,k ; V -> fp16 transposed
    {
        int tot = ROWS * HEADS * 32;
        rope_half<<<(tot + 255) / 256, 256>>>(rot, q, kv, qhp, khp);
        vtrans_kernel<<<BATCH * HEADS * 32, 256>>>(kv, vtp);
    }

    // 4) causal flash attention (fp16 m16n8k16, P in registers)
    flash5<<<dim3(SEQ / 64, BATCH * HEADS), 128, FL5_SMEM>>>(qhp, khp, vtp, ao);

    // 5) out projection (tf32; raw fp32 output)
    tf32_gemm2<<<dim3(DIM / TBN, ROWS / TBM), 256, GEMM_SMEM>>>(
        ao, wout, out, ROWS, DIM, DIM, 0);
}